// round 16
// baseline (speedup 1.0000x reference)
#include <cuda_runtime.h>
#include <math_constants.h>

#define NHAND   21
#define NPAIR   126   // 21*6
#define MAXB    8192

__constant__ int c_face[6][4] = {
    {0,1,2,3},{0,4,2,6},{0,1,4,5},{1,3,5,7},{2,3,6,7},{4,5,6,7}
};

__device__ __align__(16) float2 g_acc[MAXB];   // (num, cnt) per batch
__device__ unsigned int g_sem = 0;             // returns to 0 at end of every launch

__global__ __launch_bounds__(128, 12) void affinity_main(const float* __restrict__ poses,
                                                         float* __restrict__ out, int bs)
{
    const int tid  = threadIdx.x;
    const int lane = tid & 31;
    const int w    = tid >> 5;
    const int b    = blockIdx.x * 4 + w;          // one batch per warp

    __shared__ float  sh_pose[4][88];   // 21 hand + 8 obj, xyz
    __shared__ float  sh_co[4][72];     // per face: a(3) b(3) c(3) e(3)
    __shared__ float  sh_geo[4][12];    // p1(3) dv(3) nd(3) dvn_e thr
    __shared__ float2 s_red[4];
    __shared__ int    s_flag;

    if (b < bs) {
        const float* __restrict__ P = poses + b * 87;
        for (int i = lane; i < 87; i += 32) sh_pose[w][i] = P[i];
        __syncwarp();

        const float* O = sh_pose[w] + NHAND*3;   // obj corners, 8 x 3

        // lanes 0-5: face coeffs; lane 6: thr; lane 7: contact geometry (parallel)
        if (lane < 6) {
            int f = lane;
            int c0 = c_face[f][0], c1 = c_face[f][1], c2 = c_face[f][2], c3 = c_face[f][3];
            float* co = sh_co[w] + f*12;
            #pragma unroll
            for (int d = 0; d < 3; d++) {
                float A0 = O[c0*3+d], A1 = O[c1*3+d], A2 = O[c2*3+d], A3 = O[c3*3+d];
                co[0+d] = A2;
                co[3+d] = A3 - A2;
                co[6+d] = A0 - A2;
                co[9+d] = (A1 - A0) - (A3 - A2);
            }
        } else if (lane == 6) {
            float l1 = 0.0f, l2 = 0.0f;
            #pragma unroll
            for (int e = 0; e < 4; e++) {
                int a = e, bb = (e + 1) & 3;
                float dx = O[a*3+0] - O[bb*3+0];
                float dy = O[a*3+1] - O[bb*3+1];
                float dz = O[a*3+2] - O[bb*3+2];
                l1 += sqrtf(dx*dx + dy*dy + dz*dz);
                int a2 = a + 4, b2 = bb + 4;
                dx = O[a2*3+0] - O[b2*3+0];
                dy = O[a2*3+1] - O[b2*3+1];
                dz = O[a2*3+2] - O[b2*3+2];
                l2 += sqrtf(dx*dx + dy*dy + dz*dz);
            }
            l1 *= 0.25f; l2 *= 0.25f;
            sh_geo[w][10] = ((l1 + l2) * 0.5f) * 0.2f;   // thr
        } else if (lane == 7) {
            float p1x = (O[0]  + O[3]  + O[6]  + O[9] ) * 0.25f;
            float p1y = (O[1]  + O[4]  + O[7]  + O[10]) * 0.25f;
            float p1z = (O[2]  + O[5]  + O[8]  + O[11]) * 0.25f;
            float p2x = (O[12] + O[15] + O[18] + O[21]) * 0.25f;
            float p2y = (O[13] + O[16] + O[19] + O[22]) * 0.25f;
            float p2z = (O[14] + O[17] + O[20] + O[23]) * 0.25f;
            float dvx = p2x - p1x, dvy = p2y - p1y, dvz = p2z - p1z;
            float dvn = sqrtf(dvx*dvx + dvy*dvy + dvz*dvz);
            float dvn_e = dvn + 1e-5f;
            sh_geo[w][0] = p1x; sh_geo[w][1] = p1y; sh_geo[w][2] = p1z;
            sh_geo[w][3] = dvx; sh_geo[w][4] = dvy; sh_geo[w][5] = dvz;
            sh_geo[w][6] = dvx / dvn_e; sh_geo[w][7] = dvy / dvn_e; sh_geo[w][8] = dvz / dvn_e;
            sh_geo[w][9] = dvn_e;
        }
        __syncwarp();

        const float thr = sh_geo[w][10];

        // ---- Phase B: each lane owns pairs flat = lane+32k (k=0..3).
        //      Per u-row the quadratic in v is convex: vertex-rounded candidate. ----
        float key[4]; int argp[4];
        #pragma unroll
        for (int k = 0; k < 4; k++) {
            int flat = lane + 32*k;
            key[k] = CUDART_INF_F; argp[k] = 0;
            if (flat < NPAIR) {
                int h = flat / 6;
                int f = flat - h * 6;
                float hx = sh_pose[w][h*3], hy = sh_pose[w][h*3+1], hz = sh_pose[w][h*3+2];
                const float* co = sh_co[w] + f*12;
                float qx = co[0] - hx, qy = co[1] - hy, qz = co[2] - hz;
                float bx = co[3], by = co[4], bz = co[5];
                float cx = co[6], cy = co[7], cz = co[8];
                float ex = co[9], ey = co[10], ez = co[11];
                float best = CUDART_INF_F; int bp = 0;
                #pragma unroll
                for (int iu = 0; iu < 11; iu++) {
                    float u  = iu * 0.1f;
                    float Ax = fmaf(bx, u, qx), Ay = fmaf(by, u, qy), Az = fmaf(bz, u, qz);
                    float Bx = fmaf(ex, u, cx), By = fmaf(ey, u, cy), Bz = fmaf(ez, u, cz);
                    float m  = Ax*Bx + Ay*By + Az*Bz;
                    float C  = Bx*Bx + By*By + Bz*Bz;
                    float t  = __fdividef(-10.0f * m, C);
                    int  iv  = __float2int_rn(t);
                    iv = iv < 0 ? 0 : (iv > 10 ? 10 : iv);
                    float v  = iv * 0.1f;
                    float Wx = fmaf(Bx, v, Ax), Wy = fmaf(By, v, Ay), Wz = fmaf(Bz, v, Az);
                    float d2 = Wx*Wx + Wy*Wy + Wz*Wz;
                    if (d2 < best) { best = d2; bp = iu*11 + iv; }
                }
                key[k] = best; argp[k] = bp;
            }
        }

        // ---- Mask ballot; n = #masked ----
        int selbits = 0, n = 0;
        #pragma unroll
        for (int k = 0; k < 4; k++) {
            bool masked = (lane + 32*k < NPAIR) && (sqrtf(key[k] + 1e-6f) < thr);
            unsigned bal = __ballot_sync(0xffffffffu, masked);
            n += __popc(bal);
            if (masked) selbits |= 1 << k;
        }

        const int fast = (n <= 10);
        if (!fast) {
            // stable top-10 of the 126 keys (tie -> lower flat index)
            selbits = 0;
            float v0[4]; int i0[4];
            #pragma unroll
            for (int k = 0; k < 4; k++) {
                int t = lane + 32*k;
                if (t < NPAIR) { v0[k] = key[k]; i0[k] = t; }
                else           { v0[k] = CUDART_INF_F; i0[k] = 1 << 20; }
            }
            #pragma unroll
            for (int r = 0; r < 10; r++) {
                float bv = v0[0]; int bi = i0[0];
                #pragma unroll
                for (int k = 1; k < 4; k++)
                    if (v0[k] < bv || (v0[k] == bv && i0[k] < bi)) { bv = v0[k]; bi = i0[k]; }
                #pragma unroll
                for (int off = 16; off; off >>= 1) {
                    float ov = __shfl_xor_sync(0xffffffffu, bv, off);
                    int   oi = __shfl_xor_sync(0xffffffffu, bi, off);
                    if (ov < bv || (ov == bv && oi < bi)) { bv = ov; bi = oi; }
                }
                #pragma unroll
                for (int k = 0; k < 4; k++)
                    if (i0[k] == bi) { v0[k] = CUDART_INF_F; selbits |= 1 << k; }
            }
        }

        // ---- Contributions: owning lane computes its selected pairs ----
        float p1x = sh_geo[w][0], p1y = sh_geo[w][1], p1z = sh_geo[w][2];
        float dvx = sh_geo[w][3], dvy = sh_geo[w][4], dvz = sh_geo[w][5];
        float ndx = sh_geo[w][6], ndy = sh_geo[w][7], ndz = sh_geo[w][8];
        float dvn_e = sh_geo[w][9];

        float sx = 0.0f, sy = 0.0f, sz = 0.0f, sc = 0.0f;
        #pragma unroll
        for (int k = 0; k < 4; k++) {
            if (selbits & (1 << k)) {
                int flat = lane + 32*k;
                int h = flat / 6;
                int f = flat - h * 6;
                (void)h;
                int p  = argp[k];
                int iu = p / 11;
                int iv = p - iu * 11;
                float u = iu * 0.1f;
                float v = iv * 0.1f;
                const float* co = sh_co[w] + f*12;
                float cx = fmaf(v, fmaf(u, co[9],  co[6]),  fmaf(u, co[3], co[0]));
                float cy = fmaf(v, fmaf(u, co[10], co[7]),  fmaf(u, co[4], co[1]));
                float cz = fmaf(v, fmaf(u, co[11], co[8]),  fmaf(u, co[5], co[2]));
                float vx = cx - p1x, vy = cy - p1y, vz = cz - p1z;
                float inner = dvx*vx + dvy*vy + dvz*vz;
                float tt = inner / dvn_e;
                float rx = p1x + ndx * tt;
                float ry = p1y + ndy * tt;
                float rz = p1z + ndz * tt;
                float nx = cx - rx, ny = cy - ry, nz = cz - rz;
                float nn = sqrtf(nx*nx + ny*ny + nz*nz) + 1e-5f;
                nx /= nn; ny /= nn; nz /= nn;
                float m = 1.0f;
                if (!fast) m = (sqrtf(key[k] + 1e-6f) < thr) ? 1.0f : 0.0f;
                sx = fmaf(m, nx, sx);
                sy = fmaf(m, ny, sy);
                sz = fmaf(m, nz, sz);
                sc += m;
            }
        }
        #pragma unroll
        for (int off = 16; off; off >>= 1) {
            sx += __shfl_xor_sync(0xffffffffu, sx, off);
            sy += __shfl_xor_sync(0xffffffffu, sy, off);
            sz += __shfl_xor_sync(0xffffffffu, sz, off);
            sc += __shfl_xor_sync(0xffffffffu, sc, off);
        }
        if (lane == 0) {
            // sum_ij m_i m_j (n_i.n_j) = |sum m n|^2 ; mask.sum = (sum m)^2
            g_acc[b] = make_float2(sx*sx + sy*sy + sz*sz, sc*sc);
            __threadfence();                      // release this warp's g_acc write
        }
    }

    // ---- Block semaphore: last block performs the deterministic final reduction ----
    __syncthreads();
    if (tid == 0) {
        unsigned old = atomicAdd(&g_sem, 1u);
        s_flag = (old == gridDim.x - 1);
    }
    __syncthreads();

    if (s_flag) {
        __threadfence();                           // acquire all g_acc
        float a = 0.0f, c = 0.0f;
        const float4* __restrict__ A = (const float4*)g_acc;
        int n4 = bs >> 1;
        for (int i = tid; i < n4; i += 128) {
            float4 v = A[i];
            a += v.x + v.z;
            c += v.y + v.w;
        }
        if ((bs & 1) && tid == 0) { float2 v = g_acc[bs - 1]; a += v.x; c += v.y; }
        #pragma unroll
        for (int off = 16; off; off >>= 1) {
            a += __shfl_xor_sync(0xffffffffu, a, off);
            c += __shfl_xor_sync(0xffffffffu, c, off);
        }
        if (lane == 0) s_red[w] = make_float2(a, c);
        __syncthreads();
        if (tid == 0) {
            a = s_red[0].x + s_red[1].x + s_red[2].x + s_red[3].x;
            c = s_red[0].y + s_red[1].y + s_red[2].y + s_red[3].y;
            out[0] = a / (c + 1.0f);
            atomicExch(&g_sem, 0u);                // reset for next graph replay
        }
    }
}

extern "C" void kernel_launch(void* const* d_in, const int* in_sizes, int n_in,
                              void* d_out, int out_size)
{
    const float* poses = (const float*)d_in[0];
    int bs = in_sizes[0] / 87;
    if (bs > MAXB) bs = MAXB;
    int nblk = (bs + 3) / 4;
    affinity_main<<<nblk, 128>>>(poses, (float*)d_out, bs);
}

// round 17
// speedup vs baseline: 1.0548x; 1.0548x over previous
#include <cuda_runtime.h>
#include <math_constants.h>

#define NHAND   21
#define NPAIR   126   // 21*6
#define MAXB    8192

__constant__ int c_face[6][4] = {
    {0,1,2,3},{0,4,2,6},{0,1,4,5},{1,3,5,7},{2,3,6,7},{4,5,6,7}
};

__device__ __align__(16) float2 g_acc[MAXB];   // (num, cnt) per batch
__device__ unsigned int g_sem = 0;             // returns to 0 at end of every launch

__global__ __launch_bounds__(128, 12) void affinity_main(const float* __restrict__ poses,
                                                         float* __restrict__ out, int bs)
{
    const int tid  = threadIdx.x;
    const int lane = tid & 31;
    const int w    = tid >> 5;
    const int b    = blockIdx.x * 4 + w;          // one batch per warp

    __shared__ float  sh_pose[4][88];   // 21 hand + 8 obj, xyz
    __shared__ float  sh_co[4][72];     // per face: a(3) b(3) c(3) e(3)
    __shared__ float4 sh_row[4][66];    // per (f,iu): Bx,By,Bz, -10/C
    __shared__ float  sh_geo[4][12];    // p1(3) dv(3) nd(3) dvn_e thr
    __shared__ float2 s_red[4];
    __shared__ int    s_flag;

    if (b < bs) {
        const float* __restrict__ P = poses + b * 87;
        for (int i = lane; i < 87; i += 32) sh_pose[w][i] = P[i];
        __syncwarp();

        const float* O = sh_pose[w] + NHAND*3;   // obj corners, 8 x 3

        // lanes 0-5: face coeffs; lane 6: thr; lane 7: contact geometry (parallel)
        if (lane < 6) {
            int f = lane;
            int c0 = c_face[f][0], c1 = c_face[f][1], c2 = c_face[f][2], c3 = c_face[f][3];
            float* co = sh_co[w] + f*12;
            #pragma unroll
            for (int d = 0; d < 3; d++) {
                float A0 = O[c0*3+d], A1 = O[c1*3+d], A2 = O[c2*3+d], A3 = O[c3*3+d];
                co[0+d] = A2;
                co[3+d] = A3 - A2;
                co[6+d] = A0 - A2;
                co[9+d] = (A1 - A0) - (A3 - A2);
            }
        } else if (lane == 6) {
            float l1 = 0.0f, l2 = 0.0f;
            #pragma unroll
            for (int e = 0; e < 4; e++) {
                int a = e, bb = (e + 1) & 3;
                float dx = O[a*3+0] - O[bb*3+0];
                float dy = O[a*3+1] - O[bb*3+1];
                float dz = O[a*3+2] - O[bb*3+2];
                l1 += sqrtf(dx*dx + dy*dy + dz*dz);
                int a2 = a + 4, b2 = bb + 4;
                dx = O[a2*3+0] - O[b2*3+0];
                dy = O[a2*3+1] - O[b2*3+1];
                dz = O[a2*3+2] - O[b2*3+2];
                l2 += sqrtf(dx*dx + dy*dy + dz*dz);
            }
            l1 *= 0.25f; l2 *= 0.25f;
            sh_geo[w][10] = ((l1 + l2) * 0.5f) * 0.2f;   // thr
        } else if (lane == 7) {
            float p1x = (O[0]  + O[3]  + O[6]  + O[9] ) * 0.25f;
            float p1y = (O[1]  + O[4]  + O[7]  + O[10]) * 0.25f;
            float p1z = (O[2]  + O[5]  + O[8]  + O[11]) * 0.25f;
            float p2x = (O[12] + O[15] + O[18] + O[21]) * 0.25f;
            float p2y = (O[13] + O[16] + O[19] + O[22]) * 0.25f;
            float p2z = (O[14] + O[17] + O[20] + O[23]) * 0.25f;
            float dvx = p2x - p1x, dvy = p2y - p1y, dvz = p2z - p1z;
            float dvn = sqrtf(dvx*dvx + dvy*dvy + dvz*dvz);
            float dvn_e = dvn + 1e-5f;
            sh_geo[w][0] = p1x; sh_geo[w][1] = p1y; sh_geo[w][2] = p1z;
            sh_geo[w][3] = dvx; sh_geo[w][4] = dvy; sh_geo[w][5] = dvz;
            sh_geo[w][6] = dvx / dvn_e; sh_geo[w][7] = dvy / dvn_e; sh_geo[w][8] = dvz / dvn_e;
            sh_geo[w][9] = dvn_e;
        }
        __syncwarp();

        // ---- Row precompute: per (f,iu) store (B, -10/C). 66 entries, ~2/lane. ----
        for (int e = lane; e < 66; e += 32) {
            int f  = e / 11;
            int iu = e - f * 11;
            float u = iu * 0.1f;
            const float* co = sh_co[w] + f*12;
            float Bx = fmaf(co[9],  u, co[6]);
            float By = fmaf(co[10], u, co[7]);
            float Bz = fmaf(co[11], u, co[8]);
            float C  = Bx*Bx + By*By + Bz*Bz;
            sh_row[w][e] = make_float4(Bx, By, Bz, __fdividef(-10.0f, C));
        }
        __syncwarp();

        const float thr = sh_geo[w][10];

        // ---- Phase B: each lane owns pairs flat = lane+32k (k=0..3). ----
        float key[4]; int argp[4];
        #pragma unroll
        for (int k = 0; k < 4; k++) {
            int flat = lane + 32*k;
            key[k] = CUDART_INF_F; argp[k] = 0;
            if (flat < NPAIR) {
                int h = flat / 6;
                int f = flat - h * 6;
                float hx = sh_pose[w][h*3], hy = sh_pose[w][h*3+1], hz = sh_pose[w][h*3+2];
                const float* co = sh_co[w] + f*12;
                float qx = co[0] - hx, qy = co[1] - hy, qz = co[2] - hz;
                float bx = co[3], by = co[4], bz = co[5];
                const float4* __restrict__ row = sh_row[w] + f*11;

                float best = CUDART_INF_F;
                float bcode = 0.0f;
                #pragma unroll
                for (int iu = 0; iu < 11; iu++) {
                    float4 R = row[iu];
                    float u  = iu * 0.1f;
                    float Ax = fmaf(bx, u, qx), Ay = fmaf(by, u, qy), Az = fmaf(bz, u, qz);
                    float m  = fmaf(Az, R.z, fmaf(Ay, R.y, Ax*R.x));
                    float t  = m * R.w;                       // -10 m / C (precomputed rcp)
                    float tc = fminf(fmaxf(rintf(t), 0.0f), 10.0f);   // NaN -> 0
                    float v  = tc * 0.1f;
                    float Wx = fmaf(R.x, v, Ax), Wy = fmaf(R.y, v, Ay), Wz = fmaf(R.z, v, Az);
                    float d2 = fmaf(Wz, Wz, fmaf(Wy, Wy, Wx*Wx));
                    float code = tc + (float)(16*iu);
                    if (d2 < best) { best = d2; bcode = code; }
                }
                int ic = __float2int_rn(bcode);
                key[k]  = best;
                argp[k] = (ic >> 4) * 11 + (ic & 15);
            }
        }

        // ---- Mask ballot; n = #masked ----
        int selbits = 0, n = 0;
        #pragma unroll
        for (int k = 0; k < 4; k++) {
            bool masked = (lane + 32*k < NPAIR) && (sqrtf(key[k] + 1e-6f) < thr);
            unsigned bal = __ballot_sync(0xffffffffu, masked);
            n += __popc(bal);
            if (masked) selbits |= 1 << k;
        }

        const int fast = (n <= 10);
        if (!fast) {
            // stable top-10 of the 126 keys (tie -> lower flat index)
            selbits = 0;
            float v0[4]; int i0[4];
            #pragma unroll
            for (int k = 0; k < 4; k++) {
                int t = lane + 32*k;
                if (t < NPAIR) { v0[k] = key[k]; i0[k] = t; }
                else           { v0[k] = CUDART_INF_F; i0[k] = 1 << 20; }
            }
            #pragma unroll
            for (int r = 0; r < 10; r++) {
                float bv = v0[0]; int bi = i0[0];
                #pragma unroll
                for (int k = 1; k < 4; k++)
                    if (v0[k] < bv || (v0[k] == bv && i0[k] < bi)) { bv = v0[k]; bi = i0[k]; }
                #pragma unroll
                for (int off = 16; off; off >>= 1) {
                    float ov = __shfl_xor_sync(0xffffffffu, bv, off);
                    int   oi = __shfl_xor_sync(0xffffffffu, bi, off);
                    if (ov < bv || (ov == bv && oi < bi)) { bv = ov; bi = oi; }
                }
                #pragma unroll
                for (int k = 0; k < 4; k++)
                    if (i0[k] == bi) { v0[k] = CUDART_INF_F; selbits |= 1 << k; }
            }
        }

        // ---- Contributions: owning lane computes its selected pairs ----
        float p1x = sh_geo[w][0], p1y = sh_geo[w][1], p1z = sh_geo[w][2];
        float dvx = sh_geo[w][3], dvy = sh_geo[w][4], dvz = sh_geo[w][5];
        float ndx = sh_geo[w][6], ndy = sh_geo[w][7], ndz = sh_geo[w][8];
        float dvn_e = sh_geo[w][9];

        float sx = 0.0f, sy = 0.0f, sz = 0.0f, sc = 0.0f;
        #pragma unroll
        for (int k = 0; k < 4; k++) {
            if (selbits & (1 << k)) {
                int flat = lane + 32*k;
                int h = flat / 6;
                int f = flat - h * 6;
                (void)h;
                int p  = argp[k];
                int iu = p / 11;
                int iv = p - iu * 11;
                float u = iu * 0.1f;
                float v = iv * 0.1f;
                const float* co = sh_co[w] + f*12;
                float cx = fmaf(v, fmaf(u, co[9],  co[6]),  fmaf(u, co[3], co[0]));
                float cy = fmaf(v, fmaf(u, co[10], co[7]),  fmaf(u, co[4], co[1]));
                float cz = fmaf(v, fmaf(u, co[11], co[8]),  fmaf(u, co[5], co[2]));
                float vx = cx - p1x, vy = cy - p1y, vz = cz - p1z;
                float inner = dvx*vx + dvy*vy + dvz*vz;
                float tt = inner / dvn_e;
                float rx = p1x + ndx * tt;
                float ry = p1y + ndy * tt;
                float rz = p1z + ndz * tt;
                float nx = cx - rx, ny = cy - ry, nz = cz - rz;
                float nn = sqrtf(nx*nx + ny*ny + nz*nz) + 1e-5f;
                nx /= nn; ny /= nn; nz /= nn;
                float m = 1.0f;
                if (!fast) m = (sqrtf(key[k] + 1e-6f) < thr) ? 1.0f : 0.0f;
                sx = fmaf(m, nx, sx);
                sy = fmaf(m, ny, sy);
                sz = fmaf(m, nz, sz);
                sc += m;
            }
        }
        #pragma unroll
        for (int off = 16; off; off >>= 1) {
            sx += __shfl_xor_sync(0xffffffffu, sx, off);
            sy += __shfl_xor_sync(0xffffffffu, sy, off);
            sz += __shfl_xor_sync(0xffffffffu, sz, off);
            sc += __shfl_xor_sync(0xffffffffu, sc, off);
        }
        if (lane == 0) {
            // sum_ij m_i m_j (n_i.n_j) = |sum m n|^2 ; mask.sum = (sum m)^2
            g_acc[b] = make_float2(sx*sx + sy*sy + sz*sz, sc*sc);
            __threadfence();                      // release this warp's g_acc write
        }
    }

    // ---- Block semaphore: last block performs the deterministic final reduction ----
    __syncthreads();
    if (tid == 0) {
        unsigned old = atomicAdd(&g_sem, 1u);
        s_flag = (old == gridDim.x - 1);
    }
    __syncthreads();

    if (s_flag) {
        __threadfence();                           // acquire all g_acc
        float a = 0.0f, c = 0.0f;
        const float4* __restrict__ A = (const float4*)g_acc;
        int n4 = bs >> 1;
        for (int i = tid; i < n4; i += 128) {
            float4 v = A[i];
            a += v.x + v.z;
            c += v.y + v.w;
        }
        if ((bs & 1) && tid == 0) { float2 v = g_acc[bs - 1]; a += v.x; c += v.y; }
        #pragma unroll
        for (int off = 16; off; off >>= 1) {
            a += __shfl_xor_sync(0xffffffffu, a, off);
            c += __shfl_xor_sync(0xffffffffu, c, off);
        }
        if (lane == 0) s_red[w] = make_float2(a, c);
        __syncthreads();
        if (tid == 0) {
            a = s_red[0].x + s_red[1].x + s_red[2].x + s_red[3].x;
            c = s_red[0].y + s_red[1].y + s_red[2].y + s_red[3].y;
            out[0] = a / (c + 1.0f);
            atomicExch(&g_sem, 0u);                // reset for next graph replay
        }
    }
}

extern "C" void kernel_launch(void* const* d_in, const int* in_sizes, int n_in,
                              void* d_out, int out_size)
{
    const float* poses = (const float*)d_in[0];
    int bs = in_sizes[0] / 87;
    if (bs > MAXB) bs = MAXB;
    int nblk = (bs + 3) / 4;
    affinity_main<<<nblk, 128>>>(poses, (float*)d_out, bs);
}